// round 15
// baseline (speedup 1.0000x reference)
#include <cuda_runtime.h>
#include <cuda_fp16.h>
#include <cstdint>
#include <math.h>

#define BB 64
#define TT 4096
#define NTOT (BB*TT*64)

// ------------ device scratch ------------
__device__ double   g_red[2];
__device__ float    g_scal[4];            // cm, cs, 0.2/cm, 0.2/cs
__device__ uint32_t g_wimg[2*6144];       // B images (hi, lo), pre-swizzled fp16x2
__device__ float    g_wf[192*64];         // fp32 weights [kk = k*64+i][oc]
__device__ float    g_z0[64*1536*64];     // gauss lvl0 [b][p][oc]
__device__ float    g_z1[64*768*64];      // gauss lvl1 [b][p][oc]
__device__ float    g_xg[(size_t)64*64*6144];  // permuted x base, out layout (~100MB)
__device__ double   g_bnsp[64*256];       // per-batch BN partials
__device__ float    g_bnp[256];

#define SWZ128(o) ((o) ^ (((o) >> 3) & 0x70))

__device__ __forceinline__ uint32_t smem_u32(const void* p) {
    uint32_t a;
    asm("{ .reg .u64 t; cvta.to.shared.u64 t, %1; cvt.u32.u64 %0, t; }" : "=r"(a) : "l"(p));
    return a;
}

#define LDSM4(r, a) asm volatile( \
    "ldmatrix.sync.aligned.m8n8.x4.shared.b16 {%0,%1,%2,%3}, [%4];" \
    : "=r"((r)[0]), "=r"((r)[1]), "=r"((r)[2]), "=r"((r)[3]) : "r"(a))

#define MMA16816(d, a, b0, b1) asm volatile( \
    "mma.sync.aligned.m16n8k16.row.col.f32.f16.f16.f32 " \
    "{%0,%1,%2,%3}, {%4,%5,%6,%7}, {%8,%9}, {%0,%1,%2,%3};" \
    : "+f"((d)[0]), "+f"((d)[1]), "+f"((d)[2]), "+f"((d)[3]) \
    : "r"((a)[0]), "r"((a)[1]), "r"((a)[2]), "r"((a)[3]), "r"(b0), "r"(b1))

__device__ __forceinline__ uint32_t packsplit(float vx, float vy, uint32_t& lo) {
    __half h0 = __float2half_rn(vx); float r0 = vx - __half2float(h0);
    __half h1 = __float2half_rn(vy); float r1 = vy - __half2float(h1);
    __half g0 = __float2half_rn(r0);
    __half g1 = __float2half_rn(r1);
    lo = (uint32_t)__half_as_ushort(g0) | ((uint32_t)__half_as_ushort(g1) << 16);
    return (uint32_t)__half_as_ushort(h0) | ((uint32_t)__half_as_ushort(h1) << 16);
}

// ------------ small kernels ------------
__global__ void k_init() {
    int i = blockIdx.x * 256 + threadIdx.x;
    g_bnsp[i] = 0.0;
    if (i < 2) g_red[i] = 0.0;
}

__global__ void __launch_bounds__(256) k_reduce(const float* __restrict__ x) {
    float s = 0.f, ss = 0.f;
    const float4* x4 = (const float4*)x;
    const int n4 = NTOT / 4;
    for (int i = blockIdx.x * 256 + threadIdx.x; i < n4; i += gridDim.x * 256) {
        float4 v = x4[i];
        s  += (v.x + v.y) + (v.z + v.w);
        ss += (v.x*v.x + v.y*v.y) + (v.z*v.z + v.w*v.w);
    }
    __shared__ float r1[256], r2[256];
    int tid = threadIdx.x;
    r1[tid] = s; r2[tid] = ss; __syncthreads();
    for (int o = 128; o > 0; o >>= 1) {
        if (tid < o) { r1[tid] += r1[tid+o]; r2[tid] += r2[tid+o]; }
        __syncthreads();
    }
    if (tid == 0) {
        atomicAdd(&g_red[0], (double)r1[0]);
        atomicAdd(&g_red[1], (double)r2[0]);
    }
}

__global__ void k_wnorm(const float* __restrict__ v, const float* __restrict__ g) {
    int oc = threadIdx.x;   // 64 threads
    float s = 0.f;
    for (int kk = 0; kk < 192; kk++) { float vv = v[oc*192+kk]; s += vv*vv; }
    float sc = g[oc] / sqrtf(s);
    for (int k = 0; k < 3; k++) {
        for (int i = 0; i < 64; i++)
            g_wf[(k*64 + i)*64 + oc] = sc * v[oc*192 + i*3 + k];
        for (int ii = 0; ii < 32; ii++) {
            float w0 = sc * v[oc*192 + (2*ii)*3 + k];
            float w1 = sc * v[oc*192 + (2*ii+1)*3 + k];
            uint32_t lo, hi = packsplit(w0, w1, lo);
            int byt = (k*8 + (oc >> 3))*1024 + SWZ128((oc & 7)*128 + ii*4);
            g_wimg[byt >> 2]        = hi;
            g_wimg[6144 + (byt >> 2)] = lo;
        }
    }
    if (oc == 0) {
        double su = g_red[0], ssq = g_red[1];
        double N = (double)NTOT;
        double m = su / N;
        double var = (ssq - su*su/N) / (N - 1.0);
        g_scal[0] = (float)(0.8 / m);
        g_scal[1] = (float)(0.8 / sqrt(var));
        g_scal[2] = (float)(0.2 * m / 0.8);
        g_scal[3] = (float)(0.2 * sqrt(var) / 0.8);
    }
}

// ------------ fused conv + maxpool + gauss + BN-stats ------------
#define SM_ALO 24576
#define SM_B   49152
#define SMEM_MMA 98304

template<int LEVEL>
__device__ __forceinline__ void conv_tile(const float* __restrict__ x,
                                          const float* __restrict__ bias,
                                          char* sm, int bx, int b) {
    constexpr int L    = LEVEL ? 1024 : 2048;
    constexpr int OCL  = LEVEL ? 1533 : 3069;
    constexpr int P    = LEVEL ? 767  : 1535;
    constexpr int PSTR = LEVEL ? 768  : 1536;
    constexpr int DUP  = LEVEL ? 512  : 1024;
    float* z = LEVEL ? g_z1 : g_z0;

    const int tid = threadIdx.x, wid = tid >> 5, lane = tid & 31;
    const int o0 = bx * 64;
    const float cm = g_scal[0], cs = g_scal[1];

    {
        const uint4* wi = (const uint4*)g_wimg;
        uint4* bs = (uint4*)(sm + SM_B);
        #pragma unroll
        for (int it = 0; it < 6; it++) bs[tid + it*512] = wi[tid + it*512];
    }

    {
        const float f0c = g_scal[2], f2c = g_scal[3];
        const float2* xb2 = (const float2*)(x + (size_t)b * (TT*64));
        const int m = tid >> 3, lane8 = tid & 7;
        const int u2 = (o0 + m) * 2;
        const int r = u2 % 3;
        const int s0 = u2 / 3;
        const int mb1024 = (m >> 3) * 1024;
        const int mrow = (m & 7) * 128;
        const float f = (r == 0) ? f0c : f2c;
        #pragma unroll
        for (int k = 0; k < 3; k++) {
            int s = s0 + k;
            bool valid = (s < L);
            int tp = LEVEL ? (s << 2) : (s << 1);
            int ta = LEVEL ? (4*s + 3) : (2*s + 1);
            const float2* rp = xb2 + tp*32;
            const float2* ra = xb2 + ta*32;
            int kbase = k*8192 + mb1024;
            #pragma unroll
            for (int j = 0; j < 4; j++) {
                int ii = j*8 + lane8;
                float2 va = make_float2(0.f, 0.f);
                if (valid) {
                    float2 p = rp[ii];
                    if (r == 1) va = p;
                    else {
                        float2 a = ra[ii];
                        va.x = fmaf(f, p.x, a.x);
                        va.y = fmaf(f, p.y, a.y);
                    }
                }
                uint32_t lo, hi = packsplit(va.x, va.y, lo);
                int byt = kbase + SWZ128(mrow + ii*4);
                *(uint32_t*)(sm + byt)          = hi;
                *(uint32_t*)(sm + SM_ALO + byt) = lo;
            }
        }
    }
    __syncthreads();

    const uint32_t sbase = smem_u32(sm);
    const int wm = wid >> 2, nq = wid & 3;
    const int l16 = lane & 15, lhi = lane >> 4;

    int arow = wm*16 + l16;
    const uint32_t pa = sbase + (uint32_t)((arow >> 3)*1024)
                + ((uint32_t)(((arow & 7)*128) | (lhi*16)) ^ (uint32_t)((arow & 7) << 4));
    int brow = nq*16 + l16;
    const uint32_t pb = sbase + SM_B + (uint32_t)((brow >> 3)*1024)
                + ((uint32_t)(((brow & 7)*128) | (lhi*16)) ^ (uint32_t)((brow & 7) << 4));

    uint32_t paX[4], pbX[4];
    #pragma unroll
    for (int c = 0; c < 4; c++) { paX[c] = pa ^ (uint32_t)(c*32); pbX[c] = pb ^ (uint32_t)(c*32); }

    float dh[2][4], dxv[2][4];
    #pragma unroll
    for (int j = 0; j < 2; j++)
        #pragma unroll
        for (int q = 0; q < 4; q++) { dh[j][q] = 0.f; dxv[j][q] = 0.f; }

    #pragma unroll
    for (int s = 0; s < 12; s++) {
        uint32_t ao = (uint32_t)(s >> 2) * 8192;
        uint32_t AH[4], AL[4], BH[4], BL[4];
        uint32_t aa = paX[s & 3] + ao;
        uint32_t bb = pbX[s & 3] + ao;
        LDSM4(AH, aa); LDSM4(AL, aa + SM_ALO);
        LDSM4(BH, bb); LDSM4(BL, bb + 24576);

        MMA16816(dh[0], AH, BH[0], BH[2]);
        MMA16816(dh[1], AH, BH[1], BH[3]);
        MMA16816(dxv[0], AH, BL[0], BL[2]);
        MMA16816(dxv[1], AH, BL[1], BL[3]);
        MMA16816(dxv[0], AL, BH[0], BH[2]);
        MMA16816(dxv[1], AL, BH[1], BH[3]);
    }
    __syncthreads();

    float* tp = (float*)sm;                         // [64 oc][68]
    float* jn   = (float*)(sm + SM_ALO);            // 192 floats
    float* psum = (float*)(sm + SM_ALO + 1024);     // 8*64 floats
    {
        int m0 = wm*16 + (lane >> 2);
        int r0 = (2*(o0 + m0)) % 3;
        int r8 = (2*(o0 + m0 + 8)) % 3;
        float f0 = (r0 == 0) ? cm : ((r0 == 2) ? cs : 1.f);
        float f8 = (r8 == 0) ? cm : ((r8 == 2) ? cs : 1.f);
        #pragma unroll
        for (int nt = 0; nt < 2; nt++) {
            int oc0 = nq*16 + nt*8 + (lane & 3)*2;
            tp[oc0*68 + m0]         = f0 * (dh[nt][0] + dxv[nt][0]);
            tp[(oc0+1)*68 + m0]     = f0 * (dh[nt][1] + dxv[nt][1]);
            tp[oc0*68 + m0 + 8]     = f8 * (dh[nt][2] + dxv[nt][2]);
            tp[(oc0+1)*68 + m0 + 8] = f8 * (dh[nt][3] + dxv[nt][3]);
        }
    }
    if (tid < 192) {
        int ui = tid >> 6, i = tid & 63;
        float val = 0.f;
        if (bx > 0) {
            int u = 2*(o0 - 1) + 3*ui;
            int s = u / 3, r = u - 3*s;
            if (s < L) {
                const float* xb = x + (size_t)b * (TT*64);
                int tpi = LEVEL ? (s << 2) : (s << 1);
                float p = xb[tpi*64 + i];
                if (r == 1) val = p;
                else {
                    int ta = LEVEL ? (4*s + 3) : (2*s + 1);
                    float a = xb[ta*64 + i];
                    val = fmaf(r == 0 ? cm : cs, a, 0.2f * p);
                }
            }
        }
        jn[tid] = val;
    }
    __syncthreads();

    {
        int oc = tid & 63, part = tid >> 6;
        float sum = 0.f;
        #pragma unroll
        for (int q = 0; q < 24; q++) {
            int kk = part*24 + q;
            sum = fmaf(jn[kk], g_wf[kk*64 + oc], sum);
        }
        psum[part*64 + oc] = sum;
    }
    __syncthreads();

    float* rs = (float*)(sm + SM_ALO + 4096);
    {
        int oc = tid & 63, pg = tid >> 6;
        float bi = bias[oc];
        float bcol = -1e30f;
        if (bx > 0) {
            float s8 = 0.f;
            #pragma unroll
            for (int q = 0; q < 8; q++) s8 += psum[q*64 + oc];
            bcol = s8;
        }
        float sv = 0.f, ssv = 0.f;
        #pragma unroll
        for (int q = 0; q < 4; q++) {
            int pl = pg*4 + q;
            int p  = bx*32 + pl;
            if (p < P) {
                int i0 = 2*pl - 1;
                float v0 = (i0 < 0) ? bcol : ((o0 + i0 < OCL) ? tp[oc*68 + i0] : -1e30f);
                float v1 = (o0 + 2*pl     < OCL) ? tp[oc*68 + 2*pl]     : -1e30f;
                float v2 = (o0 + 2*pl + 1 < OCL) ? tp[oc*68 + 2*pl + 1] : -1e30f;
                float m = fmaxf(fmaxf(v0, v1), v2) + bi;
                float e  = m > 0.f ? m : expm1f(m);
                float zz = expf(-0.5f * e * e);
                z[((size_t)b*PSTR + p)*64 + oc] = zz;
                float w = (p <= DUP && !(p & 1)) ? 2.f : 1.f;
                sv += w * zz; ssv += w * zz * zz;
            }
        }
        rs[tid] = sv; rs[512 + tid] = ssv;
    }
    __syncthreads();
    if (tid < 64) {
        float s1 = 0.f, s2 = 0.f;
        #pragma unroll
        for (int q = 0; q < 8; q++) { s1 += rs[q*64 + tid]; s2 += rs[512 + q*64 + tid]; }
        atomicAdd(&g_bnsp[b*256 + LEVEL*128 + tid],      (double)s1);
        atomicAdd(&g_bnsp[b*256 + LEVEL*128 + 64 + tid], (double)s2);
    }
}

__global__ void __launch_bounds__(512, 2) k_conv_all(const float* __restrict__ x,
                                                     const float* __restrict__ bias) {
    extern __shared__ char sm[];
    int bx = blockIdx.x, b = blockIdx.y;
    if (bx < 48) conv_tile<0>(x, bias, sm, bx, b);
    else         conv_tile<1>(x, bias, sm, bx - 48, b);
}

__global__ void k_bnfin(const float* __restrict__ gamma, const float* __restrict__ beta) {
    int oc = threadIdx.x;
    #pragma unroll
    for (int l = 0; l < 2; l++) {
        double cnt = l ? 65536.0 : 131072.0;
        double su = 0.0, ssq = 0.0;
        for (int b = 0; b < 64; b++) {
            su  += g_bnsp[b*256 + l*128 + oc];
            ssq += g_bnsp[b*256 + l*128 + 64 + oc];
        }
        double mu = su / cnt;
        double var = ssq / cnt - mu*mu;
        double inv = 1.0 / sqrt(var + 1e-5);
        g_bnp[l*128 + oc]      = (float)((double)gamma[oc] * inv);
        g_bnp[l*128 + 64 + oc] = (float)((double)beta[oc] - mu * (double)gamma[oc] * inv);
    }
}

// ------------ assembly part X: x-gather/transpose -> g_xg (depends only on x) ------------
__global__ void __launch_bounds__(256) k_asm_x(const float* __restrict__ x) {
    __shared__ float tile[64][65];
    __shared__ int sT[64];
    int b  = blockIdx.y;
    int f0 = blockIdx.x * 64;
    int tid = threadIdx.x;

    if (tid < 64) {
        int f = f0 + tid;
        int part, j;
        if (f == 0)      { part = 0; j = 0; }
        else if (f == 1) { part = 1; j = 0; }
        else if (f < 5462) {
            int k = (f - 2) / 12;
            int r = (f - 2) - 12*k;
            if      (r < 4)   { part = 0; j = 9*k + 1 + r; }
            else if (r == 4)  { part = 1; j = 3*k + 1; }
            else if (r < 9)   { part = 0; j = 9*k + r; }
            else if (r == 9)  { part = 1; j = 3*k + 2; }
            else if (r == 10) { part = 0; j = 9*k + 9; }
            else              { part = 1; j = 3*k + 3; }
        } else { part = 1; j = 1366 + (f - 5462); }
        sT[tid] = (part == 0) ? j : (2*j + (j & 1));
    }
    __syncthreads();

    const float* xb = x + (size_t)b * (TT*64);
    int c = tid & 63, fg = tid >> 6;
    #pragma unroll
    for (int it = 0; it < 16; it++) {
        int fl = fg * 16 + it;
        tile[fl][c] = xb[sT[fl]*64 + c];
    }
    __syncthreads();

    #pragma unroll
    for (int it = 0; it < 16; it++) {
        int e  = it * 256 + tid;
        int cc = e >> 6, fl = e & 63;
        g_xg[((size_t)(b*64 + cc))*6144 + f0 + fl] = tile[fl][cc];
    }
}

// ------------ assembly part Y: out = g_xg + elu(bn(z)) ------------
__global__ void __launch_bounds__(256) k_asm_y(float* __restrict__ out) {
    __shared__ float ytile[64][65];
    __shared__ int sPL[64];
    int b  = blockIdx.y;
    int f0 = blockIdx.x * 64;
    int tid = threadIdx.x;

    if (tid < 64) {
        int f = f0 + tid;
        int part, j;
        if (f == 0)      { part = 0; j = 0; }
        else if (f == 1) { part = 1; j = 0; }
        else if (f < 5462) {
            int k = (f - 2) / 12;
            int r = (f - 2) - 12*k;
            if      (r < 4)   { part = 0; j = 9*k + 1 + r; }
            else if (r == 4)  { part = 1; j = 3*k + 1; }
            else if (r < 9)   { part = 0; j = 9*k + r; }
            else if (r == 9)  { part = 1; j = 3*k + 2; }
            else if (r == 10) { part = 0; j = 9*k + 9; }
            else              { part = 1; j = 3*k + 3; }
        } else { part = 1; j = 1366 + (f - 5462); }
        int pl = -1;
        if (part == 0) {
            if (j & 1) {
                int q = j >> 1;
                int p = (q < 1539) ? 2*(q/3) + ((q % 3) == 2) : q - 513;
                pl = p*2;
            }
        } else {
            if (j & 1) {
                int q = j >> 1;
                int p = (q < 771) ? 2*(q/3) + ((q % 3) == 2) : q - 257;
                pl = p*2 + 1;
            }
        }
        sPL[tid] = pl;
    }
    __syncthreads();

    for (int e = tid; e < 4096; e += 256) {
        int fl = e >> 6, cc = e & 63;
        int pl = sPL[fl];
        float y = 0.f;
        if (pl >= 0) {
            int lvl = pl & 1, p = pl >> 1;
            const float* z = lvl ? g_z1 : g_z0;
            int stride = lvl ? 768 : 1536;
            float zz = z[((size_t)b*stride + p)*64 + cc];
            float bn = fmaf(g_bnp[lvl*128 + cc], zz, g_bnp[lvl*128 + 64 + cc]);
            y = bn > 0.f ? bn : expm1f(bn);
        }
        ytile[fl][cc] = y;
    }
    __syncthreads();

    #pragma unroll
    for (int it = 0; it < 16; it++) {
        int e  = it * 256 + tid;
        int cc = e >> 6, fl = e & 63;
        size_t idx = ((size_t)(b*64 + cc))*6144 + f0 + fl;
        out[idx] = g_xg[idx] + ytile[fl][cc];
    }
}

extern "C" void kernel_launch(void* const* d_in, const int* in_sizes, int n_in,
                              void* d_out, int out_size) {
    const float* x        = (const float*)d_in[0];
    const float* conv_v   = (const float*)d_in[1];
    const float* conv_g   = (const float*)d_in[2];
    const float* conv_b   = (const float*)d_in[3];
    const float* bn_gamma = (const float*)d_in[4];
    const float* bn_beta  = (const float*)d_in[5];
    float* out = (float*)d_out;

    static cudaStream_t s_side = nullptr;
    static cudaEvent_t ev_fork = nullptr, ev_join = nullptr;
    if (s_side == nullptr) {
        cudaStreamCreate(&s_side);
        cudaEventCreateWithFlags(&ev_fork, cudaEventDisableTiming);
        cudaEventCreateWithFlags(&ev_join, cudaEventDisableTiming);
    }

    cudaFuncSetAttribute(k_conv_all, cudaFuncAttributeMaxDynamicSharedMemorySize, SMEM_MMA);

    // fork: x-permutation runs concurrently on side stream
    cudaEventRecord(ev_fork, 0);
    cudaStreamWaitEvent(s_side, ev_fork, 0);
    k_asm_x<<<dim3(96, 64), 256, 0, s_side>>>(x);
    cudaEventRecord(ev_join, s_side);

    // main chain
    k_init<<<64, 256>>>();
    k_reduce<<<1024, 256>>>(x);
    k_wnorm<<<1, 64>>>(conv_v, conv_g);
    k_conv_all<<<dim3(72, 64), 512, SMEM_MMA>>>(x, conv_b);
    k_bnfin<<<1, 64>>>(bn_gamma, bn_beta);

    // join, then final combine
    cudaStreamWaitEvent(0, ev_join, 0);
    k_asm_y<<<dim3(96, 64), 256>>>(out);
}

// round 16
// speedup vs baseline: 1.2657x; 1.2657x over previous
#include <cuda_runtime.h>
#include <cuda_fp16.h>
#include <cstdint>
#include <math.h>

#define BB 64
#define TT 4096
#define NTOT (BB*TT*64)

// ------------ device scratch ------------
__device__ double   g_red[2];
__device__ float    g_scal[4];            // cm, cs, 0.2/cm, 0.2/cs
__device__ uint32_t g_wimg[2*6144];       // B images (hi, lo), pre-swizzled fp16x2
__device__ float    g_wf[192*64];         // fp32 weights [kk = k*64+i][oc]
__device__ float    g_z0[64*1536*64];     // gauss lvl0 [b][p][oc]
__device__ float    g_z1[64*768*64];      // gauss lvl1 [b][p][oc]
__device__ double   g_bnsp[64*256];       // per-batch BN partials
__device__ float    g_bnp[256];

#define SWZ128(o) ((o) ^ (((o) >> 3) & 0x70))

__device__ __forceinline__ uint32_t smem_u32(const void* p) {
    uint32_t a;
    asm("{ .reg .u64 t; cvta.to.shared.u64 t, %1; cvt.u32.u64 %0, t; }" : "=r"(a) : "l"(p));
    return a;
}

#define LDSM4(r, a) asm volatile( \
    "ldmatrix.sync.aligned.m8n8.x4.shared.b16 {%0,%1,%2,%3}, [%4];" \
    : "=r"((r)[0]), "=r"((r)[1]), "=r"((r)[2]), "=r"((r)[3]) : "r"(a))

#define MMA16816(d, a, b0, b1) asm volatile( \
    "mma.sync.aligned.m16n8k16.row.col.f32.f16.f16.f32 " \
    "{%0,%1,%2,%3}, {%4,%5,%6,%7}, {%8,%9}, {%0,%1,%2,%3};" \
    : "+f"((d)[0]), "+f"((d)[1]), "+f"((d)[2]), "+f"((d)[3]) \
    : "r"((a)[0]), "r"((a)[1]), "r"((a)[2]), "r"((a)[3]), "r"(b0), "r"(b1))

__device__ __forceinline__ uint32_t packsplit(float vx, float vy, uint32_t& lo) {
    __half h0 = __float2half_rn(vx); float r0 = vx - __half2float(h0);
    __half h1 = __float2half_rn(vy); float r1 = vy - __half2float(h1);
    __half g0 = __float2half_rn(r0);
    __half g1 = __float2half_rn(r1);
    lo = (uint32_t)__half_as_ushort(g0) | ((uint32_t)__half_as_ushort(g1) << 16);
    return (uint32_t)__half_as_ushort(h0) | ((uint32_t)__half_as_ushort(h1) << 16);
}

// ------------ small kernels ------------
__global__ void k_init() {
    int i = blockIdx.x * 256 + threadIdx.x;
    g_bnsp[i] = 0.0;
    if (i < 2) g_red[i] = 0.0;
}

__global__ void __launch_bounds__(256) k_reduce(const float* __restrict__ x) {
    float s = 0.f, ss = 0.f;
    const float4* x4 = (const float4*)x;
    const int n4 = NTOT / 4;
    for (int i = blockIdx.x * 256 + threadIdx.x; i < n4; i += gridDim.x * 256) {
        float4 v = x4[i];
        s  += (v.x + v.y) + (v.z + v.w);
        ss += (v.x*v.x + v.y*v.y) + (v.z*v.z + v.w*v.w);
    }
    __shared__ float r1[256], r2[256];
    int tid = threadIdx.x;
    r1[tid] = s; r2[tid] = ss; __syncthreads();
    for (int o = 128; o > 0; o >>= 1) {
        if (tid < o) { r1[tid] += r1[tid+o]; r2[tid] += r2[tid+o]; }
        __syncthreads();
    }
    if (tid == 0) {
        atomicAdd(&g_red[0], (double)r1[0]);
        atomicAdd(&g_red[1], (double)r2[0]);
    }
}

// parallel weight-norm: one block per oc, 96 threads
__global__ void __launch_bounds__(96) k_wnorm(const float* __restrict__ v,
                                              const float* __restrict__ g) {
    __shared__ float ssum[3];
    __shared__ float ssc;
    const int oc = blockIdx.x;
    const int tid = threadIdx.x;
    const float* vr = v + oc*192;

    // norm reduction: 96 threads x 2 values
    float s = vr[tid]*vr[tid] + vr[tid+96]*vr[tid+96];
    #pragma unroll
    for (int o = 16; o > 0; o >>= 1)
        s += __shfl_down_sync(0xFFFFFFFFu, s, o);
    if ((tid & 31) == 0) ssum[tid >> 5] = s;
    __syncthreads();
    if (tid == 0) {
        ssc = g[oc] / sqrtf(ssum[0] + ssum[1] + ssum[2]);
        if (oc == 0) {
            double su = g_red[0], ssq = g_red[1];
            double N = (double)NTOT;
            double m = su / N;
            double var = (ssq - su*su/N) / (N - 1.0);
            g_scal[0] = (float)(0.8 / m);
            g_scal[1] = (float)(0.8 / sqrt(var));
            g_scal[2] = (float)(0.2 * m / 0.8);
            g_scal[3] = (float)(0.2 * sqrt(var) / 0.8);
        }
    }
    __syncthreads();
    const float sc = ssc;

    // each thread: one (k, ii) pair -> fp16 hi/lo images + 2 fp32 table entries
    const int k = tid >> 5, ii = tid & 31;
    float w0 = sc * vr[(2*ii)*3 + k];
    float w1 = sc * vr[(2*ii+1)*3 + k];
    g_wf[(k*64 + 2*ii)*64 + oc]     = w0;
    g_wf[(k*64 + 2*ii + 1)*64 + oc] = w1;
    uint32_t lo, hi = packsplit(w0, w1, lo);
    int byt = (k*8 + (oc >> 3))*1024 + SWZ128((oc & 7)*128 + ii*4);
    g_wimg[byt >> 2]          = hi;
    g_wimg[6144 + (byt >> 2)] = lo;
}

// ------------ fused conv + maxpool + gauss + BN-stats ------------
#define SM_ALO 24576
#define SM_B   49152
#define SMEM_MMA 98304

template<int LEVEL>
__device__ __forceinline__ void conv_tile(const float* __restrict__ x,
                                          const float* __restrict__ bias,
                                          char* sm, int bx, int b) {
    constexpr int L    = LEVEL ? 1024 : 2048;
    constexpr int OCL  = LEVEL ? 1533 : 3069;
    constexpr int P    = LEVEL ? 767  : 1535;
    constexpr int PSTR = LEVEL ? 768  : 1536;
    constexpr int DUP  = LEVEL ? 512  : 1024;
    float* z = LEVEL ? g_z1 : g_z0;

    const int tid = threadIdx.x, wid = tid >> 5, lane = tid & 31;
    const int o0 = bx * 64;
    const float cm = g_scal[0], cs = g_scal[1];

    {
        const uint4* wi = (const uint4*)g_wimg;
        uint4* bs = (uint4*)(sm + SM_B);
        #pragma unroll
        for (int it = 0; it < 6; it++) bs[tid + it*512] = wi[tid + it*512];
    }

    {
        const float f0c = g_scal[2], f2c = g_scal[3];
        const float2* xb2 = (const float2*)(x + (size_t)b * (TT*64));
        const int m = tid >> 3, lane8 = tid & 7;
        const int u2 = (o0 + m) * 2;
        const int r = u2 % 3;
        const int s0 = u2 / 3;
        const int mb1024 = (m >> 3) * 1024;
        const int mrow = (m & 7) * 128;
        const float f = (r == 0) ? f0c : f2c;
        #pragma unroll
        for (int k = 0; k < 3; k++) {
            int s = s0 + k;
            bool valid = (s < L);
            int tp = LEVEL ? (s << 2) : (s << 1);
            int ta = LEVEL ? (4*s + 3) : (2*s + 1);
            const float2* rp = xb2 + tp*32;
            const float2* ra = xb2 + ta*32;
            int kbase = k*8192 + mb1024;
            #pragma unroll
            for (int j = 0; j < 4; j++) {
                int ii = j*8 + lane8;
                float2 va = make_float2(0.f, 0.f);
                if (valid) {
                    float2 p = rp[ii];
                    if (r == 1) va = p;
                    else {
                        float2 a = ra[ii];
                        va.x = fmaf(f, p.x, a.x);
                        va.y = fmaf(f, p.y, a.y);
                    }
                }
                uint32_t lo, hi = packsplit(va.x, va.y, lo);
                int byt = kbase + SWZ128(mrow + ii*4);
                *(uint32_t*)(sm + byt)          = hi;
                *(uint32_t*)(sm + SM_ALO + byt) = lo;
            }
        }
    }
    __syncthreads();

    const uint32_t sbase = smem_u32(sm);
    const int wm = wid >> 2, nq = wid & 3;
    const int l16 = lane & 15, lhi = lane >> 4;

    int arow = wm*16 + l16;
    const uint32_t pa = sbase + (uint32_t)((arow >> 3)*1024)
                + ((uint32_t)(((arow & 7)*128) | (lhi*16)) ^ (uint32_t)((arow & 7) << 4));
    int brow = nq*16 + l16;
    const uint32_t pb = sbase + SM_B + (uint32_t)((brow >> 3)*1024)
                + ((uint32_t)(((brow & 7)*128) | (lhi*16)) ^ (uint32_t)((brow & 7) << 4));

    uint32_t paX[4], pbX[4];
    #pragma unroll
    for (int c = 0; c < 4; c++) { paX[c] = pa ^ (uint32_t)(c*32); pbX[c] = pb ^ (uint32_t)(c*32); }

    float dh[2][4], dxv[2][4];
    #pragma unroll
    for (int j = 0; j < 2; j++)
        #pragma unroll
        for (int q = 0; q < 4; q++) { dh[j][q] = 0.f; dxv[j][q] = 0.f; }

    #pragma unroll
    for (int s = 0; s < 12; s++) {
        uint32_t ao = (uint32_t)(s >> 2) * 8192;
        uint32_t AH[4], AL[4], BH[4], BL[4];
        uint32_t aa = paX[s & 3] + ao;
        uint32_t bb = pbX[s & 3] + ao;
        LDSM4(AH, aa); LDSM4(AL, aa + SM_ALO);
        LDSM4(BH, bb); LDSM4(BL, bb + 24576);

        MMA16816(dh[0], AH, BH[0], BH[2]);
        MMA16816(dh[1], AH, BH[1], BH[3]);
        MMA16816(dxv[0], AH, BL[0], BL[2]);
        MMA16816(dxv[1], AH, BL[1], BL[3]);
        MMA16816(dxv[0], AL, BH[0], BH[2]);
        MMA16816(dxv[1], AL, BH[1], BH[3]);
    }
    __syncthreads();

    float* tp = (float*)sm;                         // [64 oc][68]
    float* jn   = (float*)(sm + SM_ALO);            // 192 floats
    float* psum = (float*)(sm + SM_ALO + 1024);     // 8*64 floats
    {
        int m0 = wm*16 + (lane >> 2);
        int r0 = (2*(o0 + m0)) % 3;
        int r8 = (2*(o0 + m0 + 8)) % 3;
        float f0 = (r0 == 0) ? cm : ((r0 == 2) ? cs : 1.f);
        float f8 = (r8 == 0) ? cm : ((r8 == 2) ? cs : 1.f);
        #pragma unroll
        for (int nt = 0; nt < 2; nt++) {
            int oc0 = nq*16 + nt*8 + (lane & 3)*2;
            tp[oc0*68 + m0]         = f0 * (dh[nt][0] + dxv[nt][0]);
            tp[(oc0+1)*68 + m0]     = f0 * (dh[nt][1] + dxv[nt][1]);
            tp[oc0*68 + m0 + 8]     = f8 * (dh[nt][2] + dxv[nt][2]);
            tp[(oc0+1)*68 + m0 + 8] = f8 * (dh[nt][3] + dxv[nt][3]);
        }
    }
    if (tid < 192) {
        int ui = tid >> 6, i = tid & 63;
        float val = 0.f;
        if (bx > 0) {
            int u = 2*(o0 - 1) + 3*ui;
            int s = u / 3, r = u - 3*s;
            if (s < L) {
                const float* xb = x + (size_t)b * (TT*64);
                int tpi = LEVEL ? (s << 2) : (s << 1);
                float p = xb[tpi*64 + i];
                if (r == 1) val = p;
                else {
                    int ta = LEVEL ? (4*s + 3) : (2*s + 1);
                    float a = xb[ta*64 + i];
                    val = fmaf(r == 0 ? cm : cs, a, 0.2f * p);
                }
            }
        }
        jn[tid] = val;
    }
    __syncthreads();

    {
        int oc = tid & 63, part = tid >> 6;
        float sum = 0.f;
        #pragma unroll
        for (int q = 0; q < 24; q++) {
            int kk = part*24 + q;
            sum = fmaf(jn[kk], g_wf[kk*64 + oc], sum);
        }
        psum[part*64 + oc] = sum;
    }
    __syncthreads();

    float* rs = (float*)(sm + SM_ALO + 4096);
    {
        int oc = tid & 63, pg = tid >> 6;
        float bi = bias[oc];
        float bcol = -1e30f;
        if (bx > 0) {
            float s8 = 0.f;
            #pragma unroll
            for (int q = 0; q < 8; q++) s8 += psum[q*64 + oc];
            bcol = s8;
        }
        float sv = 0.f, ssv = 0.f;
        #pragma unroll
        for (int q = 0; q < 4; q++) {
            int pl = pg*4 + q;
            int p  = bx*32 + pl;
            if (p < P) {
                int i0 = 2*pl - 1;
                float v0 = (i0 < 0) ? bcol : ((o0 + i0 < OCL) ? tp[oc*68 + i0] : -1e30f);
                float v1 = (o0 + 2*pl     < OCL) ? tp[oc*68 + 2*pl]     : -1e30f;
                float v2 = (o0 + 2*pl + 1 < OCL) ? tp[oc*68 + 2*pl + 1] : -1e30f;
                float m = fmaxf(fmaxf(v0, v1), v2) + bi;
                float e  = m > 0.f ? m : expm1f(m);
                float zz = expf(-0.5f * e * e);
                z[((size_t)b*PSTR + p)*64 + oc] = zz;
                float w = (p <= DUP && !(p & 1)) ? 2.f : 1.f;
                sv += w * zz; ssv += w * zz * zz;
            }
        }
        rs[tid] = sv; rs[512 + tid] = ssv;
    }
    __syncthreads();
    if (tid < 64) {
        float s1 = 0.f, s2 = 0.f;
        #pragma unroll
        for (int q = 0; q < 8; q++) { s1 += rs[q*64 + tid]; s2 += rs[512 + q*64 + tid]; }
        atomicAdd(&g_bnsp[b*256 + LEVEL*128 + tid],      (double)s1);
        atomicAdd(&g_bnsp[b*256 + LEVEL*128 + 64 + tid], (double)s2);
    }
}

__global__ void __launch_bounds__(512, 2) k_conv_all(const float* __restrict__ x,
                                                     const float* __restrict__ bias) {
    extern __shared__ char sm[];
    int bx = blockIdx.x, b = blockIdx.y;
    if (bx < 48) conv_tile<0>(x, bias, sm, bx, b);
    else         conv_tile<1>(x, bias, sm, bx - 48, b);
}

// parallel BN finalize: 512 threads, 4-way batch split per (lvl, oc)
__global__ void __launch_bounds__(512) k_bnfin(const float* __restrict__ gamma,
                                               const float* __restrict__ beta) {
    __shared__ double sred[1024];
    int tid = threadIdx.x;
    int lvl = tid >> 8, rem = tid & 255;
    int oc = rem >> 2, q = rem & 3;
    double su = 0.0, ssq = 0.0;
    for (int b = q*16; b < q*16 + 16; b++) {
        su  += g_bnsp[b*256 + lvl*128 + oc];
        ssq += g_bnsp[b*256 + lvl*128 + 64 + oc];
    }
    sred[tid] = su; sred[512 + tid] = ssq;
    __syncthreads();
    if (q == 0) {
        double s1 = sred[tid] + sred[tid+1] + sred[tid+2] + sred[tid+3];
        double s2 = sred[512+tid] + sred[513+tid] + sred[514+tid] + sred[515+tid];
        double cnt = lvl ? 65536.0 : 131072.0;
        double mu = s1 / cnt;
        double var = s2 / cnt - mu*mu;
        double inv = 1.0 / sqrt(var + 1e-5);
        g_bnp[lvl*128 + oc]      = (float)((double)gamma[oc] * inv);
        g_bnp[lvl*128 + 64 + oc] = (float)((double)beta[oc] - mu * (double)gamma[oc] * inv);
    }
}

// ------------ final assembly (two-phase, fused) ------------
__global__ void __launch_bounds__(256) k_asm(const float* __restrict__ x,
                                             float* __restrict__ out) {
    __shared__ float tile[64][65];
    __shared__ float ytile[64][65];
    __shared__ int sT[64];
    __shared__ int sPL[64];
    int b  = blockIdx.y;
    int f0 = blockIdx.x * 64;
    int tid = threadIdx.x;

    if (tid < 64) {
        int f = f0 + tid;
        int part, j;
        if (f == 0)      { part = 0; j = 0; }
        else if (f == 1) { part = 1; j = 0; }
        else if (f < 5462) {
            int k = (f - 2) / 12;
            int r = (f - 2) - 12*k;
            if      (r < 4)   { part = 0; j = 9*k + 1 + r; }
            else if (r == 4)  { part = 1; j = 3*k + 1; }
            else if (r < 9)   { part = 0; j = 9*k + r; }
            else if (r == 9)  { part = 1; j = 3*k + 2; }
            else if (r == 10) { part = 0; j = 9*k + 9; }
            else              { part = 1; j = 3*k + 3; }
        } else { part = 1; j = 1366 + (f - 5462); }
        int t, pl = -1;
        if (part == 0) {
            t = j;
            if (j & 1) {
                int q = j >> 1;
                int p = (q < 1539) ? 2*(q/3) + ((q % 3) == 2) : q - 513;
                pl = p*2;
            }
        } else {
            t = 2*j + (j & 1);
            if (j & 1) {
                int q = j >> 1;
                int p = (q < 771) ? 2*(q/3) + ((q % 3) == 2) : q - 257;
                pl = p*2 + 1;
            }
        }
        sT[tid] = t; sPL[tid] = pl;
    }
    __syncthreads();

    const float* xb = x + (size_t)b * (TT*64);
    int c = tid & 63, fg = tid >> 6;
    #pragma unroll
    for (int it = 0; it < 16; it++) {
        int fl = fg * 16 + it;
        tile[fl][c] = xb[sT[fl]*64 + c];
    }

    for (int e = tid; e < 4096; e += 256) {
        int fl = e >> 6, cc = e & 63;
        int pl = sPL[fl];
        float y = 0.f;
        if (pl >= 0) {
            int lvl = pl & 1, p = pl >> 1;
            const float* z = lvl ? g_z1 : g_z0;
            int stride = lvl ? 768 : 1536;
            float zz = z[((size_t)b*stride + p)*64 + cc];
            float bn = fmaf(g_bnp[lvl*128 + cc], zz, g_bnp[lvl*128 + 64 + cc]);
            y = bn > 0.f ? bn : expm1f(bn);
        }
        ytile[fl][cc] = y;
    }
    __syncthreads();

    for (int it = 0; it < 16; it++) {
        int e  = it * 256 + tid;
        int cc = e >> 6, fl = e & 63;
        out[((size_t)(b*64 + cc))*6144 + f0 + fl] = tile[fl][cc] + ytile[fl][cc];
    }
}

extern "C" void kernel_launch(void* const* d_in, const int* in_sizes, int n_in,
                              void* d_out, int out_size) {
    const float* x        = (const float*)d_in[0];
    const float* conv_v   = (const float*)d_in[1];
    const float* conv_g   = (const float*)d_in[2];
    const float* conv_b   = (const float*)d_in[3];
    const float* bn_gamma = (const float*)d_in[4];
    const float* bn_beta  = (const float*)d_in[5];
    float* out = (float*)d_out;

    cudaFuncSetAttribute(k_conv_all, cudaFuncAttributeMaxDynamicSharedMemorySize, SMEM_MMA);

    k_init<<<64, 256>>>();
    k_reduce<<<1024, 256>>>(x);
    k_wnorm<<<64, 96>>>(conv_v, conv_g);
    k_conv_all<<<dim3(72, 64), 512, SMEM_MMA>>>(x, conv_b);
    k_bnfin<<<1, 512>>>(bn_gamma, bn_beta);
    k_asm<<<dim3(96, 64), 256>>>(x, out);
}

// round 17
// speedup vs baseline: 1.2746x; 1.0070x over previous
#include <cuda_runtime.h>
#include <cuda_fp16.h>
#include <cstdint>
#include <math.h>

#define BB 64
#define TT 4096
#define NTOT (BB*TT*64)

// ------------ device scratch ------------
__device__ double   g_red[2];
__device__ float    g_scal[4];            // cm, cs, 0.2/cm, 0.2/cs
__device__ uint32_t g_wimg[2*6144];       // B images (hi, lo), pre-swizzled fp16x2
__device__ float    g_wf[192*64];         // fp32 weights [kk = k*64+i][oc]
__device__ float    g_z0[64*1536*64];     // gauss lvl0 [b][p][oc]
__device__ float    g_z1[64*768*64];      // gauss lvl1 [b][p][oc]
__device__ double   g_bnsp[64*256];       // per-batch BN partials
__device__ float    g_bnp[256];

#define SWZ128(o) ((o) ^ (((o) >> 3) & 0x70))

__device__ __forceinline__ uint32_t smem_u32(const void* p) {
    uint32_t a;
    asm("{ .reg .u64 t; cvta.to.shared.u64 t, %1; cvt.u32.u64 %0, t; }" : "=r"(a) : "l"(p));
    return a;
}

#define LDSM4(r, a) asm volatile( \
    "ldmatrix.sync.aligned.m8n8.x4.shared.b16 {%0,%1,%2,%3}, [%4];" \
    : "=r"((r)[0]), "=r"((r)[1]), "=r"((r)[2]), "=r"((r)[3]) : "r"(a))

#define MMA16816(d, a, b0, b1) asm volatile( \
    "mma.sync.aligned.m16n8k16.row.col.f32.f16.f16.f32 " \
    "{%0,%1,%2,%3}, {%4,%5,%6,%7}, {%8,%9}, {%0,%1,%2,%3};" \
    : "+f"((d)[0]), "+f"((d)[1]), "+f"((d)[2]), "+f"((d)[3]) \
    : "r"((a)[0]), "r"((a)[1]), "r"((a)[2]), "r"((a)[3]), "r"(b0), "r"(b1))

__device__ __forceinline__ uint32_t packsplit(float vx, float vy, uint32_t& lo) {
    __half h0 = __float2half_rn(vx); float r0 = vx - __half2float(h0);
    __half h1 = __float2half_rn(vy); float r1 = vy - __half2float(h1);
    __half g0 = __float2half_rn(r0);
    __half g1 = __float2half_rn(r1);
    lo = (uint32_t)__half_as_ushort(g0) | ((uint32_t)__half_as_ushort(g1) << 16);
    return (uint32_t)__half_as_ushort(h0) | ((uint32_t)__half_as_ushort(h1) << 16);
}

// ------------ small kernels ------------
__global__ void k_init() {
    int i = blockIdx.x * 256 + threadIdx.x;
    g_bnsp[i] = 0.0;
    if (i < 2) g_red[i] = 0.0;
}

__global__ void __launch_bounds__(256) k_reduce(const float* __restrict__ x) {
    float s = 0.f, ss = 0.f;
    const float4* x4 = (const float4*)x;
    const int n4 = NTOT / 4;
    for (int i = blockIdx.x * 256 + threadIdx.x; i < n4; i += gridDim.x * 256) {
        float4 v = x4[i];
        s  += (v.x + v.y) + (v.z + v.w);
        ss += (v.x*v.x + v.y*v.y) + (v.z*v.z + v.w*v.w);
    }
    __shared__ float r1[256], r2[256];
    int tid = threadIdx.x;
    r1[tid] = s; r2[tid] = ss; __syncthreads();
    for (int o = 128; o > 0; o >>= 1) {
        if (tid < o) { r1[tid] += r1[tid+o]; r2[tid] += r2[tid+o]; }
        __syncthreads();
    }
    if (tid == 0) {
        atomicAdd(&g_red[0], (double)r1[0]);
        atomicAdd(&g_red[1], (double)r2[0]);
    }
}

// parallel weight-norm: one block per oc, 96 threads
__global__ void __launch_bounds__(96) k_wnorm(const float* __restrict__ v,
                                              const float* __restrict__ g) {
    __shared__ float ssum[3];
    __shared__ float ssc;
    const int oc = blockIdx.x;
    const int tid = threadIdx.x;
    const float* vr = v + oc*192;

    float s = vr[tid]*vr[tid] + vr[tid+96]*vr[tid+96];
    #pragma unroll
    for (int o = 16; o > 0; o >>= 1)
        s += __shfl_down_sync(0xFFFFFFFFu, s, o);
    if ((tid & 31) == 0) ssum[tid >> 5] = s;
    __syncthreads();
    if (tid == 0) {
        ssc = g[oc] / sqrtf(ssum[0] + ssum[1] + ssum[2]);
        if (oc == 0) {
            double su = g_red[0], ssq = g_red[1];
            double N = (double)NTOT;
            double m = su / N;
            double var = (ssq - su*su/N) / (N - 1.0);
            g_scal[0] = (float)(0.8 / m);
            g_scal[1] = (float)(0.8 / sqrt(var));
            g_scal[2] = (float)(0.2 * m / 0.8);
            g_scal[3] = (float)(0.2 * sqrt(var) / 0.8);
        }
    }
    __syncthreads();
    const float sc = ssc;

    const int k = tid >> 5, ii = tid & 31;
    float w0 = sc * vr[(2*ii)*3 + k];
    float w1 = sc * vr[(2*ii+1)*3 + k];
    g_wf[(k*64 + 2*ii)*64 + oc]     = w0;
    g_wf[(k*64 + 2*ii + 1)*64 + oc] = w1;
    uint32_t lo, hi = packsplit(w0, w1, lo);
    int byt = (k*8 + (oc >> 3))*1024 + SWZ128((oc & 7)*128 + ii*4);
    g_wimg[byt >> 2]          = hi;
    g_wimg[6144 + (byt >> 2)] = lo;
}

// ------------ fused conv + maxpool + gauss + BN-stats; K-split warp layout ------------
#define SM_ALO 24576
#define SM_B   49152
#define SMEM_MMA 98304

template<int LEVEL>
__device__ __forceinline__ void conv_tile(const float* __restrict__ x,
                                          const float* __restrict__ bias,
                                          char* sm, int bx, int b) {
    constexpr int L    = LEVEL ? 1024 : 2048;
    constexpr int OCL  = LEVEL ? 1533 : 3069;
    constexpr int P    = LEVEL ? 767  : 1535;
    constexpr int PSTR = LEVEL ? 768  : 1536;
    constexpr int DUP  = LEVEL ? 512  : 1024;
    float* z = LEVEL ? g_z1 : g_z0;

    const int tid = threadIdx.x, wid = tid >> 5, lane = tid & 31;
    const int o0 = bx * 64;
    const float cm = g_scal[0], cs = g_scal[1];

    {
        const uint4* wi = (const uint4*)g_wimg;
        uint4* bs = (uint4*)(sm + SM_B);
        #pragma unroll
        for (int it = 0; it < 6; it++) bs[tid + it*512] = wi[tid + it*512];
    }

    {
        const float f0c = g_scal[2], f2c = g_scal[3];
        const float2* xb2 = (const float2*)(x + (size_t)b * (TT*64));
        const int m = tid >> 3, lane8 = tid & 7;
        const int u2 = (o0 + m) * 2;
        const int r = u2 % 3;
        const int s0 = u2 / 3;
        const int mb1024 = (m >> 3) * 1024;
        const int mrow = (m & 7) * 128;
        const float f = (r == 0) ? f0c : f2c;
        #pragma unroll
        for (int k = 0; k < 3; k++) {
            int s = s0 + k;
            bool valid = (s < L);
            int tp = LEVEL ? (s << 2) : (s << 1);
            int ta = LEVEL ? (4*s + 3) : (2*s + 1);
            const float2* rp = xb2 + tp*32;
            const float2* ra = xb2 + ta*32;
            int kbase = k*8192 + mb1024;
            #pragma unroll
            for (int j = 0; j < 4; j++) {
                int ii = j*8 + lane8;
                float2 va = make_float2(0.f, 0.f);
                if (valid) {
                    float2 p = rp[ii];
                    if (r == 1) va = p;
                    else {
                        float2 a = ra[ii];
                        va.x = fmaf(f, p.x, a.x);
                        va.y = fmaf(f, p.y, a.y);
                    }
                }
                uint32_t lo, hi = packsplit(va.x, va.y, lo);
                int byt = kbase + SWZ128(mrow + ii*4);
                *(uint32_t*)(sm + byt)          = hi;
                *(uint32_t*)(sm + SM_ALO + byt) = lo;
            }
        }
    }
    __syncthreads();

    // mainloop: 16 warps = ks(2 K-halves) x wm(4, 16 rows) x nq(2, 32 oc)
    const uint32_t sbase = smem_u32(sm);
    const int ks = wid >> 3, rem = wid & 7;
    const int wm = rem >> 1, nq = rem & 1;
    const int l16 = lane & 15, lhi = lane >> 4;

    int arow = wm*16 + l16;
    const uint32_t pa = sbase + (uint32_t)((arow >> 3)*1024)
                + ((uint32_t)(((arow & 7)*128) | (lhi*16)) ^ (uint32_t)((arow & 7) << 4));
    uint32_t pbt[2];
    #pragma unroll
    for (int t = 0; t < 2; t++) {
        int brow = nq*32 + t*16 + l16;
        pbt[t] = sbase + SM_B + (uint32_t)((brow >> 3)*1024)
              + ((uint32_t)(((brow & 7)*128) | (lhi*16)) ^ (uint32_t)((brow & 7) << 4));
    }

    float dh[4][4], dxv[4][4];
    #pragma unroll
    for (int j = 0; j < 4; j++)
        #pragma unroll
        for (int q = 0; q < 4; q++) { dh[j][q] = 0.f; dxv[j][q] = 0.f; }

    const int sK = ks * 6;
    #pragma unroll
    for (int s6 = 0; s6 < 6; s6++) {
        int s = sK + s6;
        uint32_t ao = (uint32_t)(s >> 2) * 8192;
        uint32_t cb = (uint32_t)(s & 3) * 32;
        uint32_t AH[4], AL[4];
        uint32_t aa = (pa ^ cb) + ao;
        LDSM4(AH, aa); LDSM4(AL, aa + SM_ALO);
        #pragma unroll
        for (int t = 0; t < 2; t++) {
            uint32_t BH[4], BL[4];
            uint32_t bb = (pbt[t] ^ cb) + ao;
            LDSM4(BH, bb); LDSM4(BL, bb + 24576);
            MMA16816(dh[t*2+0], AH, BH[0], BH[2]);
            MMA16816(dh[t*2+1], AH, BH[1], BH[3]);
            MMA16816(dxv[t*2+0], AH, BL[0], BL[2]);
            MMA16816(dxv[t*2+1], AH, BL[1], BL[3]);
            MMA16816(dxv[t*2+0], AL, BH[0], BH[2]);
            MMA16816(dxv[t*2+1], AL, BH[1], BH[3]);
        }
    }
    __syncthreads();

    // epilogue: two-phase K-split combine into tp[oc][68]
    float* tp = (float*)sm;
    float* jn   = (float*)(sm + SM_ALO);            // 192 floats
    float* psum = (float*)(sm + SM_ALO + 1024);     // 8*64 floats
    {
        int m0 = wm*16 + (lane >> 2);
        int r0 = (2*(o0 + m0)) % 3;
        int r8 = (2*(o0 + m0 + 8)) % 3;
        float f0 = (r0 == 0) ? cm : ((r0 == 2) ? cs : 1.f);
        float f8 = (r8 == 0) ? cm : ((r8 == 2) ? cs : 1.f);
        if (ks == 0) {
            #pragma unroll
            for (int j = 0; j < 4; j++) {
                int oc0 = nq*32 + j*8 + (lane & 3)*2;
                tp[oc0*68 + m0]         = f0 * (dh[j][0] + dxv[j][0]);
                tp[(oc0+1)*68 + m0]     = f0 * (dh[j][1] + dxv[j][1]);
                tp[oc0*68 + m0 + 8]     = f8 * (dh[j][2] + dxv[j][2]);
                tp[(oc0+1)*68 + m0 + 8] = f8 * (dh[j][3] + dxv[j][3]);
            }
        }
        __syncthreads();
        if (ks == 1) {
            #pragma unroll
            for (int j = 0; j < 4; j++) {
                int oc0 = nq*32 + j*8 + (lane & 3)*2;
                tp[oc0*68 + m0]         += f0 * (dh[j][0] + dxv[j][0]);
                tp[(oc0+1)*68 + m0]     += f0 * (dh[j][1] + dxv[j][1]);
                tp[oc0*68 + m0 + 8]     += f8 * (dh[j][2] + dxv[j][2]);
                tp[(oc0+1)*68 + m0 + 8] += f8 * (dh[j][3] + dxv[j][3]);
            }
        } else if (tid < 192) {
            int ui = tid >> 6, i = tid & 63;
            float val = 0.f;
            if (bx > 0) {
                int u = 2*(o0 - 1) + 3*ui;
                int s = u / 3, r = u - 3*s;
                if (s < L) {
                    const float* xb = x + (size_t)b * (TT*64);
                    int tpi = LEVEL ? (s << 2) : (s << 1);
                    float p = xb[tpi*64 + i];
                    if (r == 1) val = p;
                    else {
                        int ta = LEVEL ? (4*s + 3) : (2*s + 1);
                        float a = xb[ta*64 + i];
                        val = fmaf(r == 0 ? cm : cs, a, 0.2f * p);
                    }
                }
            }
            jn[tid] = val;
        }
    }
    __syncthreads();

    {
        int oc = tid & 63, part = tid >> 6;
        float sum = 0.f;
        #pragma unroll
        for (int q = 0; q < 24; q++) {
            int kk = part*24 + q;
            sum = fmaf(jn[kk], g_wf[kk*64 + oc], sum);
        }
        psum[part*64 + oc] = sum;
    }
    __syncthreads();

    float* rs = (float*)(sm + SM_ALO + 4096);
    {
        int oc = tid & 63, pg = tid >> 6;
        float bi = bias[oc];
        float bcol = -1e30f;
        if (bx > 0) {
            float s8 = 0.f;
            #pragma unroll
            for (int q = 0; q < 8; q++) s8 += psum[q*64 + oc];
            bcol = s8;
        }
        float sv = 0.f, ssv = 0.f;
        #pragma unroll
        for (int q = 0; q < 4; q++) {
            int pl = pg*4 + q;
            int p  = bx*32 + pl;
            if (p < P) {
                int i0 = 2*pl - 1;
                float v0 = (i0 < 0) ? bcol : ((o0 + i0 < OCL) ? tp[oc*68 + i0] : -1e30f);
                float v1 = (o0 + 2*pl     < OCL) ? tp[oc*68 + 2*pl]     : -1e30f;
                float v2 = (o0 + 2*pl + 1 < OCL) ? tp[oc*68 + 2*pl + 1] : -1e30f;
                float m = fmaxf(fmaxf(v0, v1), v2) + bi;
                float e  = m > 0.f ? m : expm1f(m);
                float zz = expf(-0.5f * e * e);
                z[((size_t)b*PSTR + p)*64 + oc] = zz;
                float w = (p <= DUP && !(p & 1)) ? 2.f : 1.f;
                sv += w * zz; ssv += w * zz * zz;
            }
        }
        rs[tid] = sv; rs[512 + tid] = ssv;
    }
    __syncthreads();
    if (tid < 64) {
        float s1 = 0.f, s2 = 0.f;
        #pragma unroll
        for (int q = 0; q < 8; q++) { s1 += rs[q*64 + tid]; s2 += rs[512 + q*64 + tid]; }
        atomicAdd(&g_bnsp[b*256 + LEVEL*128 + tid],      (double)s1);
        atomicAdd(&g_bnsp[b*256 + LEVEL*128 + 64 + tid], (double)s2);
    }
}

__global__ void __launch_bounds__(512, 2) k_conv_all(const float* __restrict__ x,
                                                     const float* __restrict__ bias) {
    extern __shared__ char sm[];
    int bx = blockIdx.x, b = blockIdx.y;
    if (bx < 48) conv_tile<0>(x, bias, sm, bx, b);
    else         conv_tile<1>(x, bias, sm, bx - 48, b);
}

// parallel BN finalize
__global__ void __launch_bounds__(512) k_bnfin(const float* __restrict__ gamma,
                                               const float* __restrict__ beta) {
    __shared__ double sred[1024];
    int tid = threadIdx.x;
    int lvl = tid >> 8, rem = tid & 255;
    int oc = rem >> 2, q = rem & 3;
    double su = 0.0, ssq = 0.0;
    for (int b = q*16; b < q*16 + 16; b++) {
        su  += g_bnsp[b*256 + lvl*128 + oc];
        ssq += g_bnsp[b*256 + lvl*128 + 64 + oc];
    }
    sred[tid] = su; sred[512 + tid] = ssq;
    __syncthreads();
    if (q == 0) {
        double s1 = sred[tid] + sred[tid+1] + sred[tid+2] + sred[tid+3];
        double s2 = sred[512+tid] + sred[513+tid] + sred[514+tid] + sred[515+tid];
        double cnt = lvl ? 65536.0 : 131072.0;
        double mu = s1 / cnt;
        double var = s2 / cnt - mu*mu;
        double inv = 1.0 / sqrt(var + 1e-5);
        g_bnp[lvl*128 + oc]      = (float)((double)gamma[oc] * inv);
        g_bnp[lvl*128 + 64 + oc] = (float)((double)beta[oc] - mu * (double)gamma[oc] * inv);
    }
}

// ------------ final assembly (two-phase, 512 threads) ------------
__global__ void __launch_bounds__(512) k_asm(const float* __restrict__ x,
                                             float* __restrict__ out) {
    __shared__ float tile[64][65];
    __shared__ float ytile[64][65];
    __shared__ int sT[64];
    __shared__ int sPL[64];
    int b  = blockIdx.y;
    int f0 = blockIdx.x * 64;
    int tid = threadIdx.x;

    if (tid < 64) {
        int f = f0 + tid;
        int part, j;
        if (f == 0)      { part = 0; j = 0; }
        else if (f == 1) { part = 1; j = 0; }
        else if (f < 5462) {
            int k = (f - 2) / 12;
            int r = (f - 2) - 12*k;
            if      (r < 4)   { part = 0; j = 9*k + 1 + r; }
            else if (r == 4)  { part = 1; j = 3*k + 1; }
            else if (r < 9)   { part = 0; j = 9*k + r; }
            else if (r == 9)  { part = 1; j = 3*k + 2; }
            else if (r == 10) { part = 0; j = 9*k + 9; }
            else              { part = 1; j = 3*k + 3; }
        } else { part = 1; j = 1366 + (f - 5462); }
        int t, pl = -1;
        if (part == 0) {
            t = j;
            if (j & 1) {
                int q = j >> 1;
                int p = (q < 1539) ? 2*(q/3) + ((q % 3) == 2) : q - 513;
                pl = p*2;
            }
        } else {
            t = 2*j + (j & 1);
            if (j & 1) {
                int q = j >> 1;
                int p = (q < 771) ? 2*(q/3) + ((q % 3) == 2) : q - 257;
                pl = p*2 + 1;
            }
        }
        sT[tid] = t; sPL[tid] = pl;
    }
    __syncthreads();

    const float* xb = x + (size_t)b * (TT*64);
    int c = tid & 63, fg = tid >> 6;
    #pragma unroll
    for (int it = 0; it < 8; it++) {
        int fl = fg * 8 + it;
        tile[fl][c] = xb[sT[fl]*64 + c];
    }

    #pragma unroll
    for (int it = 0; it < 8; it++) {
        int e = it * 512 + tid;
        int fl = e >> 6, cc = e & 63;
        int pl = sPL[fl];
        float y = 0.f;
        if (pl >= 0) {
            int lvl = pl & 1, p = pl >> 1;
            const float* z = lvl ? g_z1 : g_z0;
            int stride = lvl ? 768 : 1536;
            float zz = z[((size_t)b*stride + p)*64 + cc];
            float bn = fmaf(g_bnp[lvl*128 + cc], zz, g_bnp[lvl*128 + 64 + cc]);
            y = bn > 0.f ? bn : expm1f(bn);
        }
        ytile[fl][cc] = y;
    }
    __syncthreads();

    #pragma unroll
    for (int it = 0; it < 8; it++) {
        int e  = it * 512 + tid;
        int cc = e >> 6, fl = e & 63;
        out[((size_t)(b*64 + cc))*6144 + f0 + fl] = tile[fl][cc] + ytile[fl][cc];
    }
}

extern "C" void kernel_launch(void* const* d_in, const int* in_sizes, int n_in,
                              void* d_out, int out_size) {
    const float* x        = (const float*)d_in[0];
    const float* conv_v   = (const float*)d_in[1];
    const float* conv_g   = (const float*)d_in[2];
    const float* conv_b   = (const float*)d_in[3];
    const float* bn_gamma = (const float*)d_in[4];
    const float* bn_beta  = (const float*)d_in[5];
    float* out = (float*)d_out;

    cudaFuncSetAttribute(k_conv_all, cudaFuncAttributeMaxDynamicSharedMemorySize, SMEM_MMA);

    k_init<<<64, 256>>>();
    k_reduce<<<1024, 256>>>(x);
    k_wnorm<<<64, 96>>>(conv_v, conv_g);
    k_conv_all<<<dim3(72, 64), 512, SMEM_MMA>>>(x, conv_b);
    k_bnfin<<<1, 512>>>(bn_gamma, bn_beta);
    k_asm<<<dim3(96, 64), 512>>>(x, out);
}